// round 9
// baseline (speedup 1.0000x reference)
#include <cuda_runtime.h>
#include <stdint.h>

// PatchShift: out[b,t,h,w,c] = x[b, (t - S[h%3, w%3]) % 8, h, w, c]
// Shapes: B=32, T=8, H=14, W=14, C=768 (fp32) -> rows of 192 float4.
// R2 structure (192-thr CTA per pixel, default cache, 64-bit idx) with 2x
// per-thread work: each CTA handles one (h,w) for TWO batches (b, b+16) ->
// 16 independent load/store pairs per thread. Offers ptxas a deeper
// software-pipeline window (more loads in flight per warp) without forcing
// registers live (R4 showed forcing hurts). Grid (196,16) = 3136 CTAs.

#define B_ 32
#define T_ 8
#define H_ 14
#define W_ 14
#define C4_ 192                         // 768 floats = 192 float4
#define TSTRIDE (H_ * W_ * C4_)         // float4 stride between time slices = 37632
#define BSTRIDE ((long long)T_ * TSTRIDE) // float4 stride between batches

__global__ __launch_bounds__(C4_) void patch_shift_kernel(
    const float4* __restrict__ x, float4* __restrict__ out)
{
    // blockIdx.x = h*14 + w (0..195), blockIdx.y = b0 (0..15); handles b0 and b0+16
    const int hw = blockIdx.x;
    const int w  = hw % 14;             // constant divisor -> mul/shift
    const int h  = hw / 14;
    const int b0 = blockIdx.y;

    const int Stab[9] = {-4, 1, 2, -1, 0, 3, -2, -3, 4};
    const int s = Stab[(h % 3) * 3 + (w % 3)];

    // base index of (b0, t=0, h, w, c4=tid)
    const long long base0 = ((long long)b0 * T_ * H_ * W_ + hw) * C4_ + threadIdx.x;
    const long long base1 = base0 + 16 * BSTRIDE;   // batch b0+16

    float4 v0[T_], v1[T_];
    #pragma unroll
    for (int t = 0; t < T_; ++t) {
        const int ts = (t - s + 8) & 7;              // source time slice
        v0[t] = x[base0 + (long long)ts * TSTRIDE];
        v1[t] = x[base1 + (long long)ts * TSTRIDE];
    }
    #pragma unroll
    for (int t = 0; t < T_; ++t) {
        out[base0 + (long long)t * TSTRIDE] = v0[t];
        out[base1 + (long long)t * TSTRIDE] = v1[t];
    }
}

extern "C" void kernel_launch(void* const* d_in, const int* in_sizes, int n_in,
                              void* d_out, int out_size)
{
    const float4* x   = (const float4*)d_in[0];
    float4*       out = (float4*)d_out;

    dim3 grid(H_ * W_, B_ / 2);         // (196, 16) = 3136 CTAs, 192 thr each
    patch_shift_kernel<<<grid, C4_>>>(x, out);
}

// round 10
// speedup vs baseline: 1.0457x; 1.0457x over previous
#include <cuda_runtime.h>
#include <stdint.h>

// PatchShift: out[b,t,h,w,c] = x[b, (t - S[h%3, w%3]) % 8, h, w, c]
// Shapes: B=32, T=8, H=14, W=14, C=768 (fp32) -> rows of 192 float4.
// FINAL — Round-2/Round-8 winner, best of 9 measured variants
// (41.5/41.95us kernel, DRAM ~77%, effective ~7.4 TB/s incl. L2 hits,
// ~93% of chip memory throughput = LTS/HBM turnaround ceiling).
// One CTA per (b,h,w); each thread copies its channel float4 across all T=8
// slices with 8 front-batched independent loads, then 8 stores.
// Measured dead ends: cache hints (ldcs/stcs, ldcg) -1.4..-2.9%; 32-bit
// indexing -2.4%; persistent 1480-CTA loop -11%; 256-thr flat -2.2%;
// 2x per-thread work -3.4%; 384-thr blocks -3.4%. ptxas' own ~4-deep
// load/store pipeline at regs=30 with ~60 warps/SM is the sweet spot.

#define B_ 32
#define T_ 8
#define H_ 14
#define W_ 14
#define C4_ 192                         // 768 floats = 192 float4
#define TSTRIDE (H_ * W_ * C4_)         // float4 stride between time slices = 37632

__global__ __launch_bounds__(C4_) void patch_shift_kernel(
    const float4* __restrict__ x, float4* __restrict__ out)
{
    // blockIdx.x = h*14 + w (0..195), blockIdx.y = b (0..31)
    const int hw = blockIdx.x;
    const int w  = hw % 14;             // constant divisor -> mul/shift
    const int h  = hw / 14;
    const int b  = blockIdx.y;

    const int Stab[9] = {-4, 1, 2, -1, 0, 3, -2, -3, 4};
    const int s = Stab[(h % 3) * 3 + (w % 3)];

    // base index of (b, t=0, h, w, c4=tid)
    const long long base = ((long long)b * T_ * H_ * W_ + hw) * C4_ + threadIdx.x;

    float4 v[T_];
    #pragma unroll
    for (int t = 0; t < T_; ++t) {
        const int ts = (t - s + 8) & 7;          // source time slice
        v[t] = x[base + (long long)ts * TSTRIDE];
    }
    #pragma unroll
    for (int t = 0; t < T_; ++t) {
        out[base + (long long)t * TSTRIDE] = v[t];
    }
}

extern "C" void kernel_launch(void* const* d_in, const int* in_sizes, int n_in,
                              void* d_out, int out_size)
{
    const float4* x   = (const float4*)d_in[0];
    float4*       out = (float4*)d_out;

    dim3 grid(H_ * W_, B_);             // (196, 32) = 6272 CTAs
    patch_shift_kernel<<<grid, C4_>>>(x, out);
}